// round 3
// baseline (speedup 1.0000x reference)
#include <cuda_runtime.h>
#include <math.h>

// ---------------------------------------------------------------------------
// Problem constants
// ---------------------------------------------------------------------------
#define B_   2
#define P_   4000
#define NP_  4096
#define D_   64
#define M_   512
#define NX_  432
#define NY_  496
#define HW_  (NX_ * NY_)          // 214272

#define S0_   ((size_t)B_ * 128 * HW_)
#define S2_   ((size_t)B_ * 64 * HW_)
#define OFF1_ (S0_)
#define OFF2_ (2 * S0_)
#define OFF3_ (2 * S0_ + S2_)                        // 137,134,080 floats to zero
#define OFF4_ (OFF3_ + (size_t)B_ * P_ * D_)

// Tiling
#define TILE_P 64
#define TILE_T 128
#define PITCH  68        // 272 B rows; conflict-free LDS.128, 16B aligned
#define NTHR   256
#define PTILES 63                       // ceil(4000/64)
#define NB_PT  (PTILES * B_)            // 126 point-attention blocks
#define NB_MEM (PTILES * B_)            // 126 memory-attention blocks
#define NB_ATT (NB_PT + NB_MEM)         // 252
#define NB_Z   296                      // zero-fill blocks
#define NB_TOT (2 * NB_ATT + (NB_Z - NB_ATT))   // 548

// dynamic shared layout (bytes)
#define SM_PL   0                                   // 64*68*4      = 17408
#define SM_PT   17408                               // 2*128*68*4   = 69632
#define SM_TKV  87040                               // 64*8*4       =  2048
#define SM_TKI  89088                               // 64*8*4       =  2048
#define SMEM_BYTES 91136

__device__ int g_winner[B_ * HW_];

// ---------------------------------------------------------------------------
__device__ __forceinline__ void cp16(void* dst, const void* src) {
    unsigned a = (unsigned)__cvta_generic_to_shared(dst);
    asm volatile("cp.async.cg.shared.global [%0], [%1], 16;" :: "r"(a), "l"(src));
}
__device__ __forceinline__ void cp_commit() {
    asm volatile("cp.async.commit_group;" ::: "memory");
}
__device__ __forceinline__ void cp_wait_all() {
    asm volatile("cp.async.wait_group 0;" ::: "memory");
}
// packed f32x2 FMA
__device__ __forceinline__ void fma2(unsigned long long& acc,
                                     unsigned long long a, unsigned long long b) {
    asm volatile("fma.rn.f32x2 %0, %1, %2, %0;" : "+l"(acc) : "l"(a), "l"(b));
}

// ---------------------------------------------------------------------------
// One attention block: 64 pillars x npts, top-8 + softmax + weighted gather.
// 256 threads = 8 warps. Warp wy owns pillars [wy*8, wy*8+8). Lane tx owns
// point rows {tx+32j}. Microtile 8x4, fp32x2-packed FMA.
// Register discipline: av loaded ONE pillar at a time (4 regs, not 32), FMAs
// ordered x-phase then y-phase so same-acc writes are 4 issues apart, dc loop
// unrolled 4x only. Target live set ~105 regs (was pinned at the 128 cap).
// ---------------------------------------------------------------------------
__device__ void attn_block(const float* __restrict__ pillars,
                           const float* __restrict__ vecs,
                           int vstride, int npts,
                           float* __restrict__ out_pos,
                           int bid, char* smem)
{
    float* s_pl  = (float*)(smem + SM_PL);
    float* s_pt  = (float*)(smem + SM_PT);
    float* s_tkv = (float*)(smem + SM_TKV);
    int*   s_tki = (int*)(smem + SM_TKI);

    const int t  = threadIdx.x;
    const int tx = t & 31;
    const int wy = t >> 5;
    const int b  = bid / PTILES;
    const int p0 = (bid % PTILES) * TILE_P;
    const int pvalid = min(TILE_P, P_ - p0);
    const float* __restrict__ vb = vecs + (size_t)b * vstride;
    const float* __restrict__ pb = pillars + ((size_t)b * P_ + p0) * D_;
    const unsigned FULL = 0xffffffffu;

    // init top-k slots
    s_tkv[t]       = -INFINITY;
    s_tkv[t + 256] = -INFINITY;

    // prefetch point tile 0
#pragma unroll
    for (int q = 0; q < 8; ++q) {
        int lin = t + q * NTHR;
        int r = lin >> 4, c = (lin & 15) << 2;
        cp16(s_pt + r * PITCH + c, vb + r * D_ + c);
    }
    cp_commit();

    // load pillar tile (zero-pad tail)
#pragma unroll
    for (int q = 0; q < 4; ++q) {
        int lin = t + q * NTHR;
        int r = lin >> 4, c = (lin & 15) << 2;
        float4 v = make_float4(0.f, 0.f, 0.f, 0.f);
        if (r < pvalid) v = *(const float4*)(pb + r * D_ + c);
        *(float4*)(s_pl + r * PITCH + c) = v;
    }
    __syncthreads();

    float vmin[8];
#pragma unroll
    for (int i = 0; i < 8; ++i) vmin[i] = -INFINITY;

    const int NT = npts / TILE_T;
    for (int tile = 0; tile < NT; ++tile) {
        float* buf = s_pt + (tile & 1) * (TILE_T * PITCH);
        cp_wait_all();
        __syncthreads();
        if (tile + 1 < NT) {
            float* nb = s_pt + ((tile + 1) & 1) * (TILE_T * PITCH);
            const float* src = vb + (size_t)(tile + 1) * TILE_T * D_;
#pragma unroll
            for (int q = 0; q < 8; ++q) {
                int lin = t + q * NTHR;
                int r = lin >> 4, c = (lin & 15) << 2;
                cp16(nb + r * PITCH + c, src + r * D_ + c);
            }
            cp_commit();
        }

        unsigned long long acc[8][4];
#pragma unroll
        for (int i = 0; i < 8; ++i)
#pragma unroll
            for (int j = 0; j < 4; ++j) acc[i][j] = 0ull;

        const float* prow = s_pl + (wy << 3) * PITCH;
#pragma unroll 4
        for (int dc = 0; dc < D_; dc += 4) {
            ulonglong2 xv[4];
#pragma unroll
            for (int j = 0; j < 4; ++j)
                xv[j] = *(const ulonglong2*)(buf + (tx + 32 * j) * PITCH + dc);
#pragma unroll
            for (int i = 0; i < 8; ++i) {
                ulonglong2 av = *(const ulonglong2*)(prow + i * PITCH + dc);
                // x-phase then y-phase: dependent same-acc writes 4 issues apart
                fma2(acc[i][0], av.x, xv[0].x);
                fma2(acc[i][1], av.x, xv[1].x);
                fma2(acc[i][2], av.x, xv[2].x);
                fma2(acc[i][3], av.x, xv[3].x);
                fma2(acc[i][0], av.y, xv[0].y);
                fma2(acc[i][1], av.y, xv[1].y);
                fma2(acc[i][2], av.y, xv[2].y);
                fma2(acc[i][3], av.y, xv[3].y);
            }
        }

        // warp-private top-8 maintenance
        const int base = tile * TILE_T;
#pragma unroll
        for (int i = 0; i < 8; ++i) {
            const int pr = (wy << 3) + i;
            float thr = vmin[i];
            float s[4];
#pragma unroll
            for (int j = 0; j < 4; ++j) {
                unsigned long long v = acc[i][j];
                s[j] = __uint_as_float((unsigned)v) +
                       __uint_as_float((unsigned)(v >> 32));
            }
            unsigned any = __ballot_sync(FULL,
                (s[0] > thr) | (s[1] > thr) | (s[2] > thr) | (s[3] > thr));
            if (any) {
                float* tv = s_tkv + pr * 8;
                int*   ti = s_tki + pr * 8;
#pragma unroll
                for (int j = 0; j < 4; ++j) {
                    unsigned m = __ballot_sync(FULL, s[j] > thr);
                    while (m) {
                        int ln = __ffs(m) - 1; m &= m - 1;
                        float v = __shfl_sync(FULL, s[j], ln);
                        if (v > thr) {       // warp-uniform
                            int slot = 0; float mn = tv[0];
#pragma unroll
                            for (int k = 1; k < 8; ++k) {
                                float x = tv[k];
                                if (x < mn) { mn = x; slot = k; }
                            }
                            tv[slot] = v;
                            ti[slot] = base + ln + 32 * j;
                            thr = tv[0];
#pragma unroll
                            for (int k = 1; k < 8; ++k) thr = fminf(thr, tv[k]);
                        }
                    }
                }
                vmin[i] = thr;
            }
        }
    }

    // epilogue: per warp, softmax over its pillars' top-8 + weighted gather
    __syncwarp();
#pragma unroll 1
    for (int i = 0; i < 8; ++i) {
        const int pr = (wy << 3) + i;
        if (pr >= pvalid) break;
        float vals[8]; int id[8];
#pragma unroll
        for (int k = 0; k < 8; ++k) { vals[k] = s_tkv[pr * 8 + k]; id[k] = s_tki[pr * 8 + k]; }
        float mx = vals[0];
#pragma unroll
        for (int k = 1; k < 8; ++k) mx = fmaxf(mx, vals[k]);
        float w[8], ssum = 0.f;
#pragma unroll
        for (int k = 0; k < 8; ++k) { w[k] = expf(vals[k] - mx); ssum += w[k]; }
        float inv = 1.f / ssum;
        float a0 = 0.f, a1 = 0.f;
#pragma unroll
        for (int k = 0; k < 8; ++k) {
            const float* vp = vb + (size_t)id[k] * D_;
            float wk = w[k] * inv;
            a0 += wk * vp[tx];
            a1 += wk * vp[tx + 32];
        }
        float* op = out_pos + ((size_t)b * P_ + p0 + pr) * D_;
        op[tx] = a0;
        op[tx + 32] = a1;
    }
}

// ---------------------------------------------------------------------------
// Fused kernel. Block roles are INTERLEAVED so wave 1 puts one attention block
// and one zero block on each SM: the DRAM-bound zero overlaps the FMA-bound
// attention instead of queueing behind it.
//   bid in [0, 504): even -> attn id bid/2, odd -> zero id bid/2
//   bid in [504, 548): zero id 252 + (bid - 504)
// ---------------------------------------------------------------------------
__global__ void __launch_bounds__(NTHR, 2)
fused_kernel(const float* __restrict__ pillars,
             const float* __restrict__ points,
             const float* __restrict__ W,
             float* __restrict__ out)
{
    extern __shared__ char smem[];
    const int bid = blockIdx.x;
    int attn_id = -1, zid;
    if (bid < 2 * NB_ATT) {
        if ((bid & 1) == 0) attn_id = bid >> 1;
        else                zid = bid >> 1;
    } else {
        zid = NB_ATT + (bid - 2 * NB_ATT);
    }

    if (attn_id >= 0) {
        const int isMem = attn_id >= NB_PT;
        const int abid = isMem ? attn_id - NB_PT : attn_id;
        attn_block(pillars,
                   isMem ? W : points,
                   isMem ? 0 : NP_ * D_,
                   isMem ? M_ : NP_,
                   out + (isMem ? OFF4_ : OFF3_),
                   abid, smem);
    } else {
        const int t = threadIdx.x;
        float4* o4 = (float4*)out;
        const size_t n4 = OFF3_ / 4;
        const size_t stride = (size_t)NB_Z * NTHR;
        const float4 z = make_float4(0.f, 0.f, 0.f, 0.f);
        for (size_t i = (size_t)zid * NTHR + t; i < n4; i += stride)
            __stcs(o4 + i, z);
        for (int i = zid * NTHR + t; i < B_ * HW_; i += NB_Z * NTHR)
            g_winner[i] = -1;
    }
}

// duplicate indices: scatter applies updates in order -> last p wins
__global__ void winner_kernel(const int* __restrict__ idx) {
    int i = blockIdx.x * blockDim.x + threadIdx.x;
    if (i < B_ * P_) {
        int b = i / P_;
        atomicMax(&g_winner[b * HW_ + idx[i]], i - b * P_);
    }
}

__global__ void scatter_kernel(const float* __restrict__ pil,
                               const float* __restrict__ scale,
                               const int* __restrict__ idx,
                               float* out) {
    int bp = blockIdx.x;                 // 0 .. B*P-1
    int b = (bp >= P_) ? 1 : 0;
    int p = bp - b * P_;
    int col = idx[bp];
    if (g_winner[b * HW_ + col] != p) return;
    int c = threadIdx.x;                 // 0..63
    float pv = pil[(size_t)bp * D_ + c];
    float sv = scale[(size_t)bp * D_ + c];
    float qv = out[OFF3_ + (size_t)bp * D_ + c];   // pos_point
    float mv = out[OFF4_ + (size_t)bp * D_ + c];   // pos_mem
    size_t g0 = (size_t)b * 128 * HW_ + (size_t)c * HW_ + col;
    out[g0] = pv;                                   // sp[:64]
    out[g0 + (size_t)64 * HW_] = mv;                // sp[64:]
    out[OFF1_ + g0] = pv;                           // sp_point[:64]
    out[OFF1_ + g0 + (size_t)64 * HW_] = qv;        // sp_point[64:]
    out[OFF2_ + (size_t)b * 64 * HW_ + (size_t)c * HW_ + col] = sv;
}

// ---------------------------------------------------------------------------
extern "C" void kernel_launch(void* const* d_in, const int* in_sizes, int n_in,
                              void* d_out, int out_size) {
    (void)in_sizes; (void)n_in; (void)out_size;
    const float* pillars = (const float*)d_in[0];
    const float* scale   = (const float*)d_in[1];
    const float* points  = (const float*)d_in[2];
    const float* W       = (const float*)d_in[3];
    const int*   idx     = (const int*)d_in[4];
    float* out = (float*)d_out;

    cudaFuncSetAttribute(fused_kernel,
                         cudaFuncAttributeMaxDynamicSharedMemorySize, SMEM_BYTES);

    fused_kernel<<<NB_TOT, NTHR, SMEM_BYTES>>>(pillars, points, W, out);
    winner_kernel<<<(B_ * P_ + 255) / 256, 256>>>(idx);
    scatter_kernel<<<B_ * P_, 64>>>(pillars, scale, idx, out);
}